// round 15
// baseline (speedup 1.0000x reference)
#include <cuda_runtime.h>
#include <cuda_bf16.h>
#include <cstdint>

// Problem constants
#define BB 4
#define TT 4096
#define DD 128
#define NF 131
static constexpr float JITTER_F = 1e-6f;
// z scale folded into exp2 domain: sqrt(log2(e)) / sqrt(128)
static constexpr float ZSCL = 0.10616492f;

// Scratch (static device globals — no runtime allocation)
__device__ __nv_bfloat16 g_zb[(size_t)BB * TT * DD];   // scaled z, bf16
__device__ float g_sq[BB * TT];                        // 0.5 * sum(z^2), exp2 domain
__device__ float g_v[BB * TT];
__device__ float g_noise[BB * TT];                     // softplus(x[130])

// ---------------------------------------------------------------------------
// Kernel 1: preprocess. One warp per row (B*T rows).
// ---------------------------------------------------------------------------
__global__ void prep_kernel(const float* __restrict__ in, float* __restrict__ out_mean) {
    int warp = threadIdx.x >> 5;
    int lane = threadIdx.x & 31;
    int row  = blockIdx.x * (blockDim.x >> 5) + warp;
    if (row >= BB * TT) return;
    const float* x = in + (size_t)row * NF;

    float sq = 0.f;
#pragma unroll
    for (int u = 0; u < 4; ++u) {
        int k = lane + 32 * u;
        float zv = x[1 + k] * ZSCL;
        sq += zv * zv;
        g_zb[(size_t)row * DD + k] = __float2bfloat16(zv);
    }
#pragma unroll
    for (int s = 16; s; s >>= 1) sq += __shfl_xor_sync(0xffffffffu, sq, s);

    if (lane == 0) {
        g_sq[row] = 0.5f * sq;
        g_v[row]  = x[NF - 2];
        float nx  = x[NF - 1];
        g_noise[row] = fmaxf(nx, 0.f) + log1pf(__expf(-fabsf(nx)));
        out_mean[row] = x[0];
    }
}

// ---------------------------------------------------------------------------
// Kernel 2: covariance. 1D grid, off-diagonal jobs first, diagonal jobs last.
// Off-diagonal CTAs write (i,j) and (j,i).
// ---------------------------------------------------------------------------
#define TILE 128
#define KC   64
#define LDS_E 72        // bf16 tile row stride: 144B, conflict-free ldmatrix
#define STRIDE_N 136    // normal-orientation staging stride (words), STS.64 conflict-free
#define STRIDE_T 132    // transposed staging stride (words), STS.32 conflict-free

#define TILE_BYTES_1 (TILE * LDS_E * 2)          // 18432 per tile buffer
#define DYN_BYTES    (4 * TILE_BYTES_1)          // 73728: As0,Bs0,As1,Bs1
#define STAGE_ONE    (32 * STRIDE_N * 4)         // 17408 (>= 32*132*4 too)

#define NTILE 32                                  // TT / TILE
#define NOFF  (NTILE * (NTILE - 1) / 2)           // 496 off-diag tiles per batch
#define NJOBS (BB * NTILE * (NTILE + 1) / 2)      // 2112

__device__ __forceinline__ void mma_bf16(float* c, const uint32_t* a, uint32_t b0, uint32_t b1) {
    asm volatile(
        "mma.sync.aligned.m16n8k16.row.col.f32.bf16.bf16.f32 "
        "{%0,%1,%2,%3}, {%4,%5,%6,%7}, {%8,%9}, {%0,%1,%2,%3};"
        : "+f"(c[0]), "+f"(c[1]), "+f"(c[2]), "+f"(c[3])
        : "r"(a[0]), "r"(a[1]), "r"(a[2]), "r"(a[3]), "r"(b0), "r"(b1));
}

__device__ __forceinline__ void cp_async16(void* smem_dst, const void* gmem_src) {
    uint32_t s = (uint32_t)__cvta_generic_to_shared(smem_dst);
    asm volatile("cp.async.cg.shared.global [%0], [%1], 16;" :: "r"(s), "l"(gmem_src));
}

using TileT = __nv_bfloat16 (*)[LDS_E];

__device__ __forceinline__ void compute_chunk(TileT As, TileT Bs,
                                              float acc[2][8][4],
                                              int wm, int wn, int lane) {
#pragma unroll
    for (int ks = 0; ks < KC; ks += 16) {
        uint32_t a[2][4];
#pragma unroll
        for (int mi = 0; mi < 2; ++mi) {
            int row = wm * 16 + mi * 64 + (lane & 15);   // interleaved mapping
            int col = ks + (lane >> 4) * 8;
            uint32_t addr = (uint32_t)__cvta_generic_to_shared(&As[row][col]);
            asm volatile("ldmatrix.sync.aligned.m8n8.x4.shared.b16 {%0,%1,%2,%3}, [%4];"
                         : "=r"(a[mi][0]), "=r"(a[mi][1]), "=r"(a[mi][2]), "=r"(a[mi][3])
                         : "r"(addr));
        }
#pragma unroll
        for (int nj = 0; nj < 4; ++nj) {
            int nrow = wn * 64 + nj * 16 + (lane & 15);
            int col  = ks + (lane >> 4) * 8;
            uint32_t addr = (uint32_t)__cvta_generic_to_shared(&Bs[nrow][col]);
            uint32_t b0, b1, b2, b3;
            asm volatile("ldmatrix.sync.aligned.m8n8.x4.shared.b16 {%0,%1,%2,%3}, [%4];"
                         : "=r"(b0), "=r"(b1), "=r"(b2), "=r"(b3)
                         : "r"(addr));
#pragma unroll
            for (int mi = 0; mi < 2; ++mi) {
                mma_bf16(acc[mi][2 * nj + 0], a[mi], b0, b2);
                mma_bf16(acc[mi][2 * nj + 1], a[mi], b1, b3);
            }
        }
    }
}

__global__ __launch_bounds__(256, 2) void cov_kernel(float* __restrict__ out_f,
                                                     float* __restrict__ out_y) {
    extern __shared__ __align__(16) unsigned char dynsm[];
    __shared__ float sSqI[TILE], sVI[TILE], sNoiseI[TILE];
    __shared__ float sSqJ[TILE], sVJ[TILE];

    auto As0 = reinterpret_cast<TileT>(dynsm);
    auto Bs0 = reinterpret_cast<TileT>(dynsm + 1 * TILE_BYTES_1);
    auto As1 = reinterpret_cast<TileT>(dynsm + 2 * TILE_BYTES_1);
    auto Bs1 = reinterpret_cast<TileT>(dynsm + 3 * TILE_BYTES_1);
    float* stg0 = reinterpret_cast<float*>(dynsm);
    float* stg1 = reinterpret_cast<float*>(dynsm + STAGE_ONE);

    // Decode job: off-diagonal jobs [0, BB*NOFF), diagonal jobs afterwards
    int job = blockIdx.x;
    int b, ti, tj;
    bool diag_tile;
    if (job < BB * NOFF) {
        b = job / NOFF;
        int r = job - b * NOFF;
        ti = 0;
        while (r >= NTILE - 1 - ti) { r -= NTILE - 1 - ti; ++ti; }
        tj = ti + 1 + r;
        diag_tile = false;
    } else {
        int d = job - BB * NOFF;
        b = d >> 5;
        ti = tj = d & 31;
        diag_tile = true;
    }
    const int i0 = ti * TILE;
    const int j0 = tj * TILE;

    const int tid  = threadIdx.x;
    const int warp = tid >> 5;
    const int lane = tid & 31;
    const int wm = warp >> 1;   // 0..3 -> 16-row strip pair (mi selects half)
    const int wn = warp & 1;    // 0..1 -> 64-col strip
    const int r4 = lane >> 2;
    const int c2 = (lane & 3) * 2;

    if (tid < TILE) {
        int gi = b * TT + i0 + tid;
        sSqI[tid] = g_sq[gi]; sVI[tid] = g_v[gi]; sNoiseI[tid] = g_noise[gi];
        int gj = b * TT + j0 + tid;
        sSqJ[tid] = g_sq[gj]; sVJ[tid] = g_v[gj];
    }

    const __nv_bfloat16* zbase = g_zb + (size_t)b * TT * DD;

    // Prefetch both k-chunks as two cp.async groups
#pragma unroll
    for (int r = 0; r < 4; ++r) {
        int idx = tid + 256 * r;
        int row = idx >> 3;
        int vec = idx & 7;
        cp_async16(&As0[row][vec * 8], zbase + (size_t)(i0 + row) * DD + 0  + vec * 8);
        cp_async16(&Bs0[row][vec * 8], zbase + (size_t)(j0 + row) * DD + 0  + vec * 8);
    }
    asm volatile("cp.async.commit_group;");
#pragma unroll
    for (int r = 0; r < 4; ++r) {
        int idx = tid + 256 * r;
        int row = idx >> 3;
        int vec = idx & 7;
        cp_async16(&As1[row][vec * 8], zbase + (size_t)(i0 + row) * DD + KC + vec * 8);
        cp_async16(&Bs1[row][vec * 8], zbase + (size_t)(j0 + row) * DD + KC + vec * 8);
    }
    asm volatile("cp.async.commit_group;");

    float acc[2][8][4];
#pragma unroll
    for (int mi = 0; mi < 2; ++mi)
#pragma unroll
        for (int nj = 0; nj < 8; ++nj)
#pragma unroll
            for (int q = 0; q < 4; ++q) acc[mi][nj][q] = 0.f;

    asm volatile("cp.async.wait_group 1;");
    __syncthreads();
    compute_chunk(As0, Bs0, acc, wm, wn, lane);

    asm volatile("cp.async.wait_group 0;");
    __syncthreads();
    compute_chunk(As1, Bs1, acc, wm, wn, lane);

    // ---- Epilogue phase 1: gram -> f values (exp2 domain, sq pre-halved) ----
#pragma unroll
    for (int mi = 0; mi < 2; ++mi) {
#pragma unroll
        for (int nj = 0; nj < 8; ++nj) {
            int jloc = wn * 64 + nj * 8 + c2;
            float sqj0 = sSqJ[jloc],     sqj1 = sSqJ[jloc + 1];
            float vj0  = sVJ[jloc],      vj1  = sVJ[jloc + 1];
#pragma unroll
            for (int h = 0; h < 2; ++h) {
                int iloc = wm * 16 + mi * 64 + h * 8 + r4;   // interleaved mapping
                float sqi = sSqI[iloc], vi = sVI[iloc];
                float e0 = exp2f(acc[mi][nj][2 * h + 0] - sqi - sqj0) * vi * vj0;
                float e1 = exp2f(acc[mi][nj][2 * h + 1] - sqi - sqj1) * vi * vj1;
                if (diag_tile) {
                    if (iloc == jloc)     e0 += JITTER_F;
                    if (iloc == jloc + 1) e1 += JITTER_F;
                }
                acc[mi][nj][2 * h + 0] = e0;
                acc[mi][nj][2 * h + 1] = e1;
            }
        }
    }

    const size_t matoff = (size_t)b * TT * TT;
    float* fo = out_f + matoff;
    float* yo = out_y + matoff;
    const int nchunks = diag_tile ? 4 : 8;

    __syncthreads(); // mainloop smem reads complete before staging overwrite

    for (int ch = 0; ch < nchunks; ++ch) {
        float* st = (ch & 1) ? stg1 : stg0;
        const int stride = (ch < 4) ? STRIDE_N : STRIDE_T;

        if (ch < 4) {
            // Chunk ch rows 32ch..32ch+31 = { wm*16 + mi*64 : mi=ch>>1, wm>>1==ch&1 }
            if ((wm >> 1) == (ch & 1)) {
                const int mi = ch >> 1;
#pragma unroll
                for (int nj = 0; nj < 8; ++nj) {
                    int col = wn * 64 + nj * 8 + c2;
#pragma unroll
                    for (int h = 0; h < 2; ++h) {
                        int row = (wm & 1) * 16 + h * 8 + r4; // 0..31 within chunk
                        *reinterpret_cast<float2*>(&st[row * STRIDE_N + col]) =
                            make_float2(acc[mi][nj][2 * h + 0], acc[mi][nj][2 * h + 1]);
                    }
                }
            }
        } else {
            // Transposed chunk: j-rows 32(ch-4)..+31; writers wn == (ch-4)>>1
            int chp = ch - 4;
            if (wn == (chp >> 1)) {
                int njb = (chp & 1) * 4;
#pragma unroll
                for (int mi = 0; mi < 2; ++mi)
#pragma unroll
                    for (int njl = 0; njl < 4; ++njl) {
                        int nj = njb + njl;
                        int jr = njl * 8 + c2;
#pragma unroll
                        for (int h = 0; h < 2; ++h) {
                            int iloc = wm * 16 + mi * 64 + h * 8 + r4; // 0..127
                            st[jr * STRIDE_T + iloc]       = acc[mi][nj][2 * h + 0];
                            st[(jr + 1) * STRIDE_T + iloc] = acc[mi][nj][2 * h + 1];
                        }
                    }
            }
        }
        __syncthreads();

        const int orow0 = (ch < 4) ? (i0 + ch * 32) : (j0 + (ch - 4) * 32);
        const int ocol0 = (ch < 4) ? j0 : i0;
#pragma unroll
        for (int r = 0; r < 4; ++r) {
            int idx = tid + 256 * r;
            int row = idx >> 5;
            int c4  = idx & 31;
            float4 v = *reinterpret_cast<const float4*>(&st[row * stride + c4 * 4]);
            int i  = orow0 + row;
            int jb = ocol0 + c4 * 4;
            size_t off = (size_t)i * TT + jb;
            __stcs(reinterpret_cast<float4*>(&fo[off]), v);
            if (diag_tile) {
                int d = i - jb;
                if ((unsigned)d < 4u) {
                    float ni = sNoiseI[ch * 32 + row];
                    if (d == 0) v.x += ni;
                    else if (d == 1) v.y += ni;
                    else if (d == 2) v.z += ni;
                    else v.w += ni;
                }
            }
            __stcs(reinterpret_cast<float4*>(&yo[off]), v);
        }
        // Double buffer: this buffer is only rewritten after the NEXT barrier.
    }
}

// ---------------------------------------------------------------------------
extern "C" void kernel_launch(void* const* d_in, const int* in_sizes, int n_in,
                              void* d_out, int out_size) {
    const float* in = (const float*)d_in[0];
    float* out = (float*)d_out;

    float* out_mean = out;                                    // B*T
    float* out_f    = out + (size_t)BB * TT;                  // B*T*T
    float* out_y    = out_f + (size_t)BB * TT * TT;           // B*T*T

    cudaFuncSetAttribute(cov_kernel, cudaFuncAttributeMaxDynamicSharedMemorySize, DYN_BYTES);

    prep_kernel<<<(BB * TT) / 8, 256>>>(in, out_mean);

    cov_kernel<<<NJOBS, 256, DYN_BYTES>>>(out_f, out_y);
}

// round 16
// speedup vs baseline: 1.5093x; 1.5093x over previous
#include <cuda_runtime.h>
#include <cuda_bf16.h>
#include <cstdint>

// Problem constants
#define BB 4
#define TT 4096
#define DD 128
#define NF 131
static constexpr float JITTER_F = 1e-6f;
// z scale folded into exp2 domain: sqrt(log2(e)) / sqrt(128)
static constexpr float ZSCL = 0.10616492f;

// Scratch (static device globals — no runtime allocation)
__device__ __nv_bfloat16 g_zb[(size_t)BB * TT * DD];   // scaled z, bf16
__device__ float g_sq[BB * TT];                        // 0.5 * sum(z^2), exp2 domain
__device__ float g_v[BB * TT];
__device__ float g_noise[BB * TT];                     // softplus(x[130])

// ---------------------------------------------------------------------------
// Kernel 1: preprocess. One warp per row (B*T rows).
// ---------------------------------------------------------------------------
__global__ void prep_kernel(const float* __restrict__ in, float* __restrict__ out_mean) {
    int warp = threadIdx.x >> 5;
    int lane = threadIdx.x & 31;
    int row  = blockIdx.x * (blockDim.x >> 5) + warp;
    if (row >= BB * TT) return;
    const float* x = in + (size_t)row * NF;

    float sq = 0.f;
#pragma unroll
    for (int u = 0; u < 4; ++u) {
        int k = lane + 32 * u;
        float zv = x[1 + k] * ZSCL;
        sq += zv * zv;
        g_zb[(size_t)row * DD + k] = __float2bfloat16(zv);
    }
#pragma unroll
    for (int s = 16; s; s >>= 1) sq += __shfl_xor_sync(0xffffffffu, sq, s);

    if (lane == 0) {
        g_sq[row] = 0.5f * sq;
        g_v[row]  = x[NF - 2];
        float nx  = x[NF - 1];
        g_noise[row] = fmaxf(nx, 0.f) + log1pf(__expf(-fabsf(nx)));
        out_mean[row] = x[0];
    }
}

// ---------------------------------------------------------------------------
// Kernel 2: covariance. 1D grid, off-diagonal jobs first, diagonal jobs last.
// Off-diagonal CTAs write (i,j) and (j,i).
// ---------------------------------------------------------------------------
#define TILE 128
#define KC   64
#define LDS_E 72        // bf16 tile row stride: 144B, conflict-free ldmatrix
#define STRIDE_N 136    // normal-orientation staging stride (words), STS.64 conflict-free
#define STRIDE_T 132    // transposed staging stride (words), STS.32 conflict-free

#define TILE_BYTES_1 (TILE * LDS_E * 2)          // 18432 per tile buffer
#define DYN_BYTES    (4 * TILE_BYTES_1)          // 73728: As0,Bs0,As1,Bs1
#define STAGE_ONE    (32 * STRIDE_N * 4)         // 17408 (>= 32*132*4 too)

#define NTILE 32                                  // TT / TILE
#define NOFF  (NTILE * (NTILE - 1) / 2)           // 496 off-diag tiles per batch
#define NJOBS (BB * NTILE * (NTILE + 1) / 2)      // 2112

__device__ __forceinline__ void mma_bf16(float* c, const uint32_t* a, uint32_t b0, uint32_t b1) {
    asm volatile(
        "mma.sync.aligned.m16n8k16.row.col.f32.bf16.bf16.f32 "
        "{%0,%1,%2,%3}, {%4,%5,%6,%7}, {%8,%9}, {%0,%1,%2,%3};"
        : "+f"(c[0]), "+f"(c[1]), "+f"(c[2]), "+f"(c[3])
        : "r"(a[0]), "r"(a[1]), "r"(a[2]), "r"(a[3]), "r"(b0), "r"(b1));
}

__device__ __forceinline__ void cp_async16(void* smem_dst, const void* gmem_src) {
    uint32_t s = (uint32_t)__cvta_generic_to_shared(smem_dst);
    asm volatile("cp.async.cg.shared.global [%0], [%1], 16;" :: "r"(s), "l"(gmem_src));
}

using TileT = __nv_bfloat16 (*)[LDS_E];

__device__ __forceinline__ void compute_chunk(TileT As, TileT Bs,
                                              float acc[2][8][4],
                                              int wm, int wn, int lane) {
#pragma unroll
    for (int ks = 0; ks < KC; ks += 16) {
        uint32_t a[2][4];
#pragma unroll
        for (int mi = 0; mi < 2; ++mi) {
            int row = wm * 16 + mi * 64 + (lane & 15);   // interleaved mapping
            int col = ks + (lane >> 4) * 8;
            uint32_t addr = (uint32_t)__cvta_generic_to_shared(&As[row][col]);
            asm volatile("ldmatrix.sync.aligned.m8n8.x4.shared.b16 {%0,%1,%2,%3}, [%4];"
                         : "=r"(a[mi][0]), "=r"(a[mi][1]), "=r"(a[mi][2]), "=r"(a[mi][3])
                         : "r"(addr));
        }
#pragma unroll
        for (int nj = 0; nj < 4; ++nj) {
            int nrow = wn * 64 + nj * 16 + (lane & 15);
            int col  = ks + (lane >> 4) * 8;
            uint32_t addr = (uint32_t)__cvta_generic_to_shared(&Bs[nrow][col]);
            uint32_t b0, b1, b2, b3;
            asm volatile("ldmatrix.sync.aligned.m8n8.x4.shared.b16 {%0,%1,%2,%3}, [%4];"
                         : "=r"(b0), "=r"(b1), "=r"(b2), "=r"(b3)
                         : "r"(addr));
#pragma unroll
            for (int mi = 0; mi < 2; ++mi) {
                mma_bf16(acc[mi][2 * nj + 0], a[mi], b0, b2);
                mma_bf16(acc[mi][2 * nj + 1], a[mi], b1, b3);
            }
        }
    }
}

__global__ __launch_bounds__(256, 2) void cov_kernel(float* __restrict__ out_f,
                                                     float* __restrict__ out_y) {
    extern __shared__ __align__(16) unsigned char dynsm[];
    __shared__ float sSqI[TILE], sVI[TILE], sNoiseI[TILE];
    __shared__ float sSqJ[TILE], sVJ[TILE];

    auto As0 = reinterpret_cast<TileT>(dynsm);
    auto Bs0 = reinterpret_cast<TileT>(dynsm + 1 * TILE_BYTES_1);
    auto As1 = reinterpret_cast<TileT>(dynsm + 2 * TILE_BYTES_1);
    auto Bs1 = reinterpret_cast<TileT>(dynsm + 3 * TILE_BYTES_1);
    float* stg0 = reinterpret_cast<float*>(dynsm);
    float* stg1 = reinterpret_cast<float*>(dynsm + STAGE_ONE);

    // Decode job: off-diagonal jobs [0, BB*NOFF), diagonal jobs afterwards
    int job = blockIdx.x;
    int b, ti, tj;
    bool diag_tile;
    if (job < BB * NOFF) {
        b = job / NOFF;
        int r = job - b * NOFF;
        ti = 0;
        while (r >= NTILE - 1 - ti) { r -= NTILE - 1 - ti; ++ti; }
        tj = ti + 1 + r;
        diag_tile = false;
    } else {
        int d = job - BB * NOFF;
        b = d >> 5;
        ti = tj = d & 31;
        diag_tile = true;
    }
    const int i0 = ti * TILE;
    const int j0 = tj * TILE;

    const int tid  = threadIdx.x;
    const int warp = tid >> 5;
    const int lane = tid & 31;
    const int wm = warp >> 1;   // 0..3 -> 16-row strip pair (mi selects half)
    const int wn = warp & 1;    // 0..1 -> 64-col strip
    const int r4 = lane >> 2;
    const int c2 = (lane & 3) * 2;

    if (tid < TILE) {
        int gi = b * TT + i0 + tid;
        sSqI[tid] = g_sq[gi]; sVI[tid] = g_v[gi]; sNoiseI[tid] = g_noise[gi];
        int gj = b * TT + j0 + tid;
        sSqJ[tid] = g_sq[gj]; sVJ[tid] = g_v[gj];
    }

    const __nv_bfloat16* zbase = g_zb + (size_t)b * TT * DD;

    // Prefetch both k-chunks as two cp.async groups
#pragma unroll
    for (int r = 0; r < 4; ++r) {
        int idx = tid + 256 * r;
        int row = idx >> 3;
        int vec = idx & 7;
        cp_async16(&As0[row][vec * 8], zbase + (size_t)(i0 + row) * DD + 0  + vec * 8);
        cp_async16(&Bs0[row][vec * 8], zbase + (size_t)(j0 + row) * DD + 0  + vec * 8);
    }
    asm volatile("cp.async.commit_group;");
#pragma unroll
    for (int r = 0; r < 4; ++r) {
        int idx = tid + 256 * r;
        int row = idx >> 3;
        int vec = idx & 7;
        cp_async16(&As1[row][vec * 8], zbase + (size_t)(i0 + row) * DD + KC + vec * 8);
        cp_async16(&Bs1[row][vec * 8], zbase + (size_t)(j0 + row) * DD + KC + vec * 8);
    }
    asm volatile("cp.async.commit_group;");

    float acc[2][8][4];
#pragma unroll
    for (int mi = 0; mi < 2; ++mi)
#pragma unroll
        for (int nj = 0; nj < 8; ++nj)
#pragma unroll
            for (int q = 0; q < 4; ++q) acc[mi][nj][q] = 0.f;

    asm volatile("cp.async.wait_group 1;");
    __syncthreads();
    compute_chunk(As0, Bs0, acc, wm, wn, lane);

    asm volatile("cp.async.wait_group 0;");
    __syncthreads();
    compute_chunk(As1, Bs1, acc, wm, wn, lane);

    // ---- Epilogue phase 1: gram -> f values (exp2 domain, sq pre-halved) ----
#pragma unroll
    for (int mi = 0; mi < 2; ++mi) {
#pragma unroll
        for (int nj = 0; nj < 8; ++nj) {
            int jloc = wn * 64 + nj * 8 + c2;
            float sqj0 = sSqJ[jloc],     sqj1 = sSqJ[jloc + 1];
            float vj0  = sVJ[jloc],      vj1  = sVJ[jloc + 1];
#pragma unroll
            for (int h = 0; h < 2; ++h) {
                int iloc = wm * 16 + mi * 64 + h * 8 + r4;   // interleaved mapping
                float sqi = sSqI[iloc], vi = sVI[iloc];
                float e0 = exp2f(acc[mi][nj][2 * h + 0] - sqi - sqj0) * vi * vj0;
                float e1 = exp2f(acc[mi][nj][2 * h + 1] - sqi - sqj1) * vi * vj1;
                if (diag_tile) {
                    if (iloc == jloc)     e0 += JITTER_F;
                    if (iloc == jloc + 1) e1 += JITTER_F;
                }
                acc[mi][nj][2 * h + 0] = e0;
                acc[mi][nj][2 * h + 1] = e1;
            }
        }
    }

    const size_t matoff = (size_t)b * TT * TT;
    float* fo = out_f + matoff;
    float* yo = out_y + matoff;
    const int nchunks = diag_tile ? 4 : 8;

    __syncthreads(); // mainloop smem reads complete before staging overwrite

    for (int ch = 0; ch < nchunks; ++ch) {
        float* st = (ch & 1) ? stg1 : stg0;
        const int stride = (ch < 4) ? STRIDE_N : STRIDE_T;

        if (ch < 4) {
            // Chunk ch rows 32ch..32ch+31 = { wm*16 + mi*64 : mi=ch>>1, wm>>1==ch&1 }
            if ((wm >> 1) == (ch & 1)) {
                const int mi = ch >> 1;
#pragma unroll
                for (int nj = 0; nj < 8; ++nj) {
                    int col = wn * 64 + nj * 8 + c2;
#pragma unroll
                    for (int h = 0; h < 2; ++h) {
                        int row = (wm & 1) * 16 + h * 8 + r4; // 0..31 within chunk
                        *reinterpret_cast<float2*>(&st[row * STRIDE_N + col]) =
                            make_float2(acc[mi][nj][2 * h + 0], acc[mi][nj][2 * h + 1]);
                    }
                }
            }
        } else {
            // Transposed chunk: j-rows 32(ch-4)..+31; writers wn == (ch-4)>>1
            int chp = ch - 4;
            if (wn == (chp >> 1)) {
                int njb = (chp & 1) * 4;
#pragma unroll
                for (int mi = 0; mi < 2; ++mi)
#pragma unroll
                    for (int njl = 0; njl < 4; ++njl) {
                        int nj = njb + njl;
                        int jr = njl * 8 + c2;
#pragma unroll
                        for (int h = 0; h < 2; ++h) {
                            int iloc = wm * 16 + mi * 64 + h * 8 + r4; // 0..127
                            st[jr * STRIDE_T + iloc]       = acc[mi][nj][2 * h + 0];
                            st[(jr + 1) * STRIDE_T + iloc] = acc[mi][nj][2 * h + 1];
                        }
                    }
            }
        }
        __syncthreads();

        const int orow0 = (ch < 4) ? (i0 + ch * 32) : (j0 + (ch - 4) * 32);
        const int ocol0 = (ch < 4) ? j0 : i0;
#pragma unroll
        for (int r = 0; r < 4; ++r) {
            int idx = tid + 256 * r;
            int row = idx >> 5;
            int c4  = idx & 31;
            float4 v = *reinterpret_cast<const float4*>(&st[row * stride + c4 * 4]);
            int i  = orow0 + row;
            int jb = ocol0 + c4 * 4;
            size_t off = (size_t)i * TT + jb;
            __stcs(reinterpret_cast<float4*>(&fo[off]), v);
            if (diag_tile) {
                int d = i - jb;
                if ((unsigned)d < 4u) {
                    float ni = sNoiseI[ch * 32 + row];
                    if (d == 0) v.x += ni;
                    else if (d == 1) v.y += ni;
                    else if (d == 2) v.z += ni;
                    else v.w += ni;
                }
            }
            __stcs(reinterpret_cast<float4*>(&yo[off]), v);
        }
        // Double buffer: this buffer is only rewritten after the NEXT barrier.
    }
}

// ---------------------------------------------------------------------------
extern "C" void kernel_launch(void* const* d_in, const int* in_sizes, int n_in,
                              void* d_out, int out_size) {
    const float* in = (const float*)d_in[0];
    float* out = (float*)d_out;

    float* out_mean = out;                                    // B*T
    float* out_f    = out + (size_t)BB * TT;                  // B*T*T
    float* out_y    = out_f + (size_t)BB * TT * TT;           // B*T*T

    cudaFuncSetAttribute(cov_kernel, cudaFuncAttributeMaxDynamicSharedMemorySize, DYN_BYTES);

    prep_kernel<<<(BB * TT) / 8, 256>>>(in, out_mean);

    cov_kernel<<<NJOBS, 256, DYN_BYTES>>>(out_f, out_y);
}

// round 17
// speedup vs baseline: 1.5188x; 1.0063x over previous
#include <cuda_runtime.h>
#include <cuda_bf16.h>
#include <cstdint>

// Problem constants
#define BB 4
#define TT 4096
#define DD 128
#define NF 131
static constexpr float JITTER_F = 1e-6f;
// z scale folded into exp2 domain: sqrt(log2(e)) / sqrt(128)
static constexpr float ZSCL = 0.10616492f;

// Scratch (static device globals — no runtime allocation)
__device__ __nv_bfloat16 g_zb[(size_t)BB * TT * DD];   // scaled z, bf16
__device__ float g_sq[BB * TT];                        // 0.5 * sum(z^2), exp2 domain
__device__ float g_v[BB * TT];
__device__ float g_noise[BB * TT];                     // softplus(x[130])

// ---------------------------------------------------------------------------
// Kernel 1: preprocess. One warp per row (B*T rows).
// ---------------------------------------------------------------------------
__global__ void prep_kernel(const float* __restrict__ in, float* __restrict__ out_mean) {
    int warp = threadIdx.x >> 5;
    int lane = threadIdx.x & 31;
    int row  = blockIdx.x * (blockDim.x >> 5) + warp;
    if (row >= BB * TT) return;
    const float* x = in + (size_t)row * NF;

    float sq = 0.f;
#pragma unroll
    for (int u = 0; u < 4; ++u) {
        int k = lane + 32 * u;
        float zv = x[1 + k] * ZSCL;
        sq += zv * zv;
        g_zb[(size_t)row * DD + k] = __float2bfloat16(zv);
    }
#pragma unroll
    for (int s = 16; s; s >>= 1) sq += __shfl_xor_sync(0xffffffffu, sq, s);

    if (lane == 0) {
        g_sq[row] = 0.5f * sq;
        g_v[row]  = x[NF - 2];
        float nx  = x[NF - 1];
        g_noise[row] = fmaxf(nx, 0.f) + log1pf(__expf(-fabsf(nx)));
        out_mean[row] = x[0];
    }
}

// ---------------------------------------------------------------------------
// Kernel 2: covariance. 1D grid, off-diagonal jobs first, diagonal jobs last.
// Off-diagonal CTAs write (i,j) and (j,i).
// ---------------------------------------------------------------------------
#define TILE 128
#define KC   64
#define LDS_E 72        // bf16 tile row stride: 144B, conflict-free ldmatrix
#define STRIDE_N 136    // normal-orientation staging stride (words), STS.64 conflict-free
#define STRIDE_T 132    // transposed staging stride (words), STS.32 conflict-free

#define TILE_BYTES_1 (TILE * LDS_E * 2)          // 18432 per tile buffer
#define DYN_BYTES    (4 * TILE_BYTES_1)          // 73728: As0,Bs0,As1,Bs1
#define STAGE_ONE    (32 * STRIDE_N * 4)         // 17408 (>= 32*132*4 too)

#define NTILE 32                                  // TT / TILE
#define NOFF  (NTILE * (NTILE - 1) / 2)           // 496 off-diag tiles per batch
#define NJOBS (BB * NTILE * (NTILE + 1) / 2)      // 2112

__device__ __forceinline__ void mma_bf16(float* c, const uint32_t* a, uint32_t b0, uint32_t b1) {
    asm volatile(
        "mma.sync.aligned.m16n8k16.row.col.f32.bf16.bf16.f32 "
        "{%0,%1,%2,%3}, {%4,%5,%6,%7}, {%8,%9}, {%0,%1,%2,%3};"
        : "+f"(c[0]), "+f"(c[1]), "+f"(c[2]), "+f"(c[3])
        : "r"(a[0]), "r"(a[1]), "r"(a[2]), "r"(a[3]), "r"(b0), "r"(b1));
}

__device__ __forceinline__ void cp_async16(void* smem_dst, const void* gmem_src) {
    uint32_t s = (uint32_t)__cvta_generic_to_shared(smem_dst);
    asm volatile("cp.async.cg.shared.global [%0], [%1], 16;" :: "r"(s), "l"(gmem_src));
}

using TileT = __nv_bfloat16 (*)[LDS_E];

__device__ __forceinline__ void compute_chunk(TileT As, TileT Bs,
                                              float acc[2][8][4],
                                              int wm, int wn, int lane) {
#pragma unroll
    for (int ks = 0; ks < KC; ks += 16) {
        uint32_t a[2][4];
#pragma unroll
        for (int mi = 0; mi < 2; ++mi) {
            int row = wm * 16 + mi * 64 + (lane & 15);   // interleaved mapping
            int col = ks + (lane >> 4) * 8;
            uint32_t addr = (uint32_t)__cvta_generic_to_shared(&As[row][col]);
            asm volatile("ldmatrix.sync.aligned.m8n8.x4.shared.b16 {%0,%1,%2,%3}, [%4];"
                         : "=r"(a[mi][0]), "=r"(a[mi][1]), "=r"(a[mi][2]), "=r"(a[mi][3])
                         : "r"(addr));
        }
#pragma unroll
        for (int nj = 0; nj < 4; ++nj) {
            int nrow = wn * 64 + nj * 16 + (lane & 15);
            int col  = ks + (lane >> 4) * 8;
            uint32_t addr = (uint32_t)__cvta_generic_to_shared(&Bs[nrow][col]);
            uint32_t b0, b1, b2, b3;
            asm volatile("ldmatrix.sync.aligned.m8n8.x4.shared.b16 {%0,%1,%2,%3}, [%4];"
                         : "=r"(b0), "=r"(b1), "=r"(b2), "=r"(b3)
                         : "r"(addr));
#pragma unroll
            for (int mi = 0; mi < 2; ++mi) {
                mma_bf16(acc[mi][2 * nj + 0], a[mi], b0, b2);
                mma_bf16(acc[mi][2 * nj + 1], a[mi], b1, b3);
            }
        }
    }
}

__global__ __launch_bounds__(256, 2) void cov_kernel(float* __restrict__ out_f,
                                                     float* __restrict__ out_y) {
    extern __shared__ __align__(16) unsigned char dynsm[];
    __shared__ float sSqI[TILE], sVI[TILE], sNoiseI[TILE];
    __shared__ float sSqJ[TILE], sVJ[TILE];

    auto As0 = reinterpret_cast<TileT>(dynsm);
    auto Bs0 = reinterpret_cast<TileT>(dynsm + 1 * TILE_BYTES_1);
    auto As1 = reinterpret_cast<TileT>(dynsm + 2 * TILE_BYTES_1);
    auto Bs1 = reinterpret_cast<TileT>(dynsm + 3 * TILE_BYTES_1);
    float* stg0 = reinterpret_cast<float*>(dynsm);
    float* stg1 = reinterpret_cast<float*>(dynsm + STAGE_ONE);

    // Decode job: off-diagonal jobs [0, BB*NOFF), diagonal jobs afterwards
    int job = blockIdx.x;
    int b, ti, tj;
    bool diag_tile;
    if (job < BB * NOFF) {
        b = job / NOFF;
        int r = job - b * NOFF;
        ti = 0;
        while (r >= NTILE - 1 - ti) { r -= NTILE - 1 - ti; ++ti; }
        tj = ti + 1 + r;
        diag_tile = false;
    } else {
        int d = job - BB * NOFF;
        b = d >> 5;
        ti = tj = d & 31;
        diag_tile = true;
    }
    const int i0 = ti * TILE;
    const int j0 = tj * TILE;

    const int tid  = threadIdx.x;
    const int warp = tid >> 5;
    const int lane = tid & 31;
    const int wm = warp >> 1;   // 0..3 -> 16-row strip pair (mi selects half)
    const int wn = warp & 1;    // 0..1 -> 64-col strip
    const int r4 = lane >> 2;
    const int c2 = (lane & 3) * 2;

    const __nv_bfloat16* zbase = g_zb + (size_t)b * TT * DD;

    // Tile prefetch FIRST (both k-chunks, two cp.async groups) so no thread's
    // cp.async issue is delayed behind the param LDG->STS scoreboard stall.
#pragma unroll
    for (int r = 0; r < 4; ++r) {
        int idx = tid + 256 * r;
        int row = idx >> 3;
        int vec = idx & 7;
        cp_async16(&As0[row][vec * 8], zbase + (size_t)(i0 + row) * DD + 0  + vec * 8);
        cp_async16(&Bs0[row][vec * 8], zbase + (size_t)(j0 + row) * DD + 0  + vec * 8);
    }
    asm volatile("cp.async.commit_group;");
#pragma unroll
    for (int r = 0; r < 4; ++r) {
        int idx = tid + 256 * r;
        int row = idx >> 3;
        int vec = idx & 7;
        cp_async16(&As1[row][vec * 8], zbase + (size_t)(i0 + row) * DD + KC + vec * 8);
        cp_async16(&Bs1[row][vec * 8], zbase + (size_t)(j0 + row) * DD + KC + vec * 8);
    }
    asm volatile("cp.async.commit_group;");

    // Param loads now overlap the bulk tile-load latency.
    if (tid < TILE) {
        int gi = b * TT + i0 + tid;
        sSqI[tid] = g_sq[gi]; sVI[tid] = g_v[gi]; sNoiseI[tid] = g_noise[gi];
        int gj = b * TT + j0 + tid;
        sSqJ[tid] = g_sq[gj]; sVJ[tid] = g_v[gj];
    }

    float acc[2][8][4];
#pragma unroll
    for (int mi = 0; mi < 2; ++mi)
#pragma unroll
        for (int nj = 0; nj < 8; ++nj)
#pragma unroll
            for (int q = 0; q < 4; ++q) acc[mi][nj][q] = 0.f;

    asm volatile("cp.async.wait_group 1;");
    __syncthreads();
    compute_chunk(As0, Bs0, acc, wm, wn, lane);

    asm volatile("cp.async.wait_group 0;");
    __syncthreads();
    compute_chunk(As1, Bs1, acc, wm, wn, lane);

    // ---- Epilogue phase 1: gram -> f values (exp2 domain, sq pre-halved) ----
#pragma unroll
    for (int mi = 0; mi < 2; ++mi) {
#pragma unroll
        for (int nj = 0; nj < 8; ++nj) {
            int jloc = wn * 64 + nj * 8 + c2;
            float sqj0 = sSqJ[jloc],     sqj1 = sSqJ[jloc + 1];
            float vj0  = sVJ[jloc],      vj1  = sVJ[jloc + 1];
#pragma unroll
            for (int h = 0; h < 2; ++h) {
                int iloc = wm * 16 + mi * 64 + h * 8 + r4;   // interleaved mapping
                float sqi = sSqI[iloc], vi = sVI[iloc];
                float e0 = exp2f(acc[mi][nj][2 * h + 0] - sqi - sqj0) * vi * vj0;
                float e1 = exp2f(acc[mi][nj][2 * h + 1] - sqi - sqj1) * vi * vj1;
                if (diag_tile) {
                    if (iloc == jloc)     e0 += JITTER_F;
                    if (iloc == jloc + 1) e1 += JITTER_F;
                }
                acc[mi][nj][2 * h + 0] = e0;
                acc[mi][nj][2 * h + 1] = e1;
            }
        }
    }

    const size_t matoff = (size_t)b * TT * TT;
    float* fo = out_f + matoff;
    float* yo = out_y + matoff;
    const int nchunks = diag_tile ? 4 : 8;

    __syncthreads(); // mainloop smem reads complete before staging overwrite

    for (int ch = 0; ch < nchunks; ++ch) {
        float* st = (ch & 1) ? stg1 : stg0;
        const int stride = (ch < 4) ? STRIDE_N : STRIDE_T;

        if (ch < 4) {
            // Chunk ch rows 32ch..32ch+31 = { wm*16 + mi*64 : mi=ch>>1, wm>>1==ch&1 }
            if ((wm >> 1) == (ch & 1)) {
                const int mi = ch >> 1;
#pragma unroll
                for (int nj = 0; nj < 8; ++nj) {
                    int col = wn * 64 + nj * 8 + c2;
#pragma unroll
                    for (int h = 0; h < 2; ++h) {
                        int row = (wm & 1) * 16 + h * 8 + r4; // 0..31 within chunk
                        *reinterpret_cast<float2*>(&st[row * STRIDE_N + col]) =
                            make_float2(acc[mi][nj][2 * h + 0], acc[mi][nj][2 * h + 1]);
                    }
                }
            }
        } else {
            // Transposed chunk: j-rows 32(ch-4)..+31; writers wn == (ch-4)>>1
            int chp = ch - 4;
            if (wn == (chp >> 1)) {
                int njb = (chp & 1) * 4;
#pragma unroll
                for (int mi = 0; mi < 2; ++mi)
#pragma unroll
                    for (int njl = 0; njl < 4; ++njl) {
                        int nj = njb + njl;
                        int jr = njl * 8 + c2;
#pragma unroll
                        for (int h = 0; h < 2; ++h) {
                            int iloc = wm * 16 + mi * 64 + h * 8 + r4; // 0..127
                            st[jr * STRIDE_T + iloc]       = acc[mi][nj][2 * h + 0];
                            st[(jr + 1) * STRIDE_T + iloc] = acc[mi][nj][2 * h + 1];
                        }
                    }
            }
        }
        __syncthreads();

        const int orow0 = (ch < 4) ? (i0 + ch * 32) : (j0 + (ch - 4) * 32);
        const int ocol0 = (ch < 4) ? j0 : i0;
#pragma unroll
        for (int r = 0; r < 4; ++r) {
            int idx = tid + 256 * r;
            int row = idx >> 5;
            int c4  = idx & 31;
            float4 v = *reinterpret_cast<const float4*>(&st[row * stride + c4 * 4]);
            int i  = orow0 + row;
            int jb = ocol0 + c4 * 4;
            size_t off = (size_t)i * TT + jb;
            __stcs(reinterpret_cast<float4*>(&fo[off]), v);
            if (diag_tile) {
                int d = i - jb;
                if ((unsigned)d < 4u) {
                    float ni = sNoiseI[ch * 32 + row];
                    if (d == 0) v.x += ni;
                    else if (d == 1) v.y += ni;
                    else if (d == 2) v.z += ni;
                    else v.w += ni;
                }
            }
            __stcs(reinterpret_cast<float4*>(&yo[off]), v);
        }
        // Double buffer: this buffer is only rewritten after the NEXT barrier.
    }
}

// ---------------------------------------------------------------------------
extern "C" void kernel_launch(void* const* d_in, const int* in_sizes, int n_in,
                              void* d_out, int out_size) {
    const float* in = (const float*)d_in[0];
    float* out = (float*)d_out;

    float* out_mean = out;                                    // B*T
    float* out_f    = out + (size_t)BB * TT;                  // B*T*T
    float* out_y    = out_f + (size_t)BB * TT * TT;           // B*T*T

    cudaFuncSetAttribute(cov_kernel, cudaFuncAttributeMaxDynamicSharedMemorySize, DYN_BYTES);

    prep_kernel<<<(BB * TT) / 8, 256>>>(in, out_mean);

    cov_kernel<<<NJOBS, 256, DYN_BYTES>>>(out_f, out_y);
}